// round 4
// baseline (speedup 1.0000x reference)
#include <cuda_runtime.h>
#include <cuda_bf16.h>

// Problem constants
#define N 4096
#define D 512
#define NC 100          // real classes
#define NCP 128         // padded classes
#define ROWS_B 32       // rows per GEMM block
#define KT 32           // k-tile
#define NBLK (N / ROWS_B)   // 128 compute blocks
#define NCLEAN 14           // cleaner blocks (128+14=142 <= 148 SMs, all resident)

// Packed fp32x2 FMA (Blackwell)
#define FMA2(d, a, b) \
    asm("fma.rn.f32x2 %0, %1, %2, %3;" : "=l"(d) : "l"(a), "l"(b), "l"(d))
#define SPLAT2(d, f) \
    asm("mov.b64 %0, {%1, %1};" : "=l"(d) : "f"(f))

// Scratch (device globals; zero-initialized at module load, self-cleaned per replay)
__device__ float  g_rscale[N];                    // per-row 1/||txt_i||
__device__ __align__(16) float g_G[NC * D];       // class sums of img_n, [c][d]
__device__ int    g_cnt[NCP];                     // class counts
__device__ double g_neg;                          // neg_similarity accumulator
__device__ double g_sumd;                         // sum_i d_i
__device__ double g_sumexpd;                      // sum_i exp(d_i)
__device__ unsigned int g_tickG;                  // "done reading G" ticket
__device__ unsigned int g_fin;                    // epilogue ticket
__device__ unsigned int g_cleandone;              // cleaner completion ticket

// ---------------------------------------------------------------------------
// Kernel 1: per-row: norms, d_i, scatter img_n into G, counts, scalar sums.
// grid = N blocks, 128 threads (thread owns 4 consecutive dims, float4)
// ---------------------------------------------------------------------------
__global__ void __launch_bounds__(128) rownorm_kernel(
    const float* __restrict__ img,
    const float* __restrict__ txt,
    const int* __restrict__ labels)
{
    const int i    = blockIdx.x;
    const int tid  = threadIdx.x;
    const int lane = tid & 31;
    const int warp = tid >> 5;

    const float4 a = reinterpret_cast<const float4*>(img + (size_t)i * D)[tid];
    const float4 b = reinterpret_cast<const float4*>(txt + (size_t)i * D)[tid];

    float sii = a.x*a.x + a.y*a.y + a.z*a.z + a.w*a.w;
    float stt = b.x*b.x + b.y*b.y + b.z*b.z + b.w*b.w;
    float sit = a.x*b.x + a.y*b.y + a.z*b.z + a.w*b.w;

    #pragma unroll
    for (int off = 16; off > 0; off >>= 1) {
        sii += __shfl_xor_sync(0xffffffffu, sii, off);
        stt += __shfl_xor_sync(0xffffffffu, stt, off);
        sit += __shfl_xor_sync(0xffffffffu, sit, off);
    }
    __shared__ float red[3][4];
    if (lane == 0) { red[0][warp] = sii; red[1][warp] = stt; red[2][warp] = sit; }
    __syncthreads();
    sii = red[0][0] + red[0][1] + red[0][2] + red[0][3];
    stt = red[1][0] + red[1][1] + red[1][2] + red[1][3];
    sit = red[2][0] + red[2][1] + red[2][2] + red[2][3];

    const float rimg = rsqrtf(sii);
    const float rtxt = rsqrtf(stt);
    int c = labels[i];
    c = min(max(c, 0), NC - 1);

    // scatter normalized image row into class sum G[c][:] (coalesced REDG)
    float* gc = g_G + (size_t)c * D + tid * 4;
    atomicAdd(gc + 0, a.x * rimg);
    atomicAdd(gc + 1, a.y * rimg);
    atomicAdd(gc + 2, a.z * rimg);
    atomicAdd(gc + 3, a.w * rimg);

    if (tid == 0) {
        g_rscale[i] = rtxt;
        const float d = sit * rimg * rtxt;
        atomicAdd(&g_cnt[c], 1);
        atomicAdd(&g_sumd, (double)d);
        atomicAdd(&g_sumexpd, (double)expf(d));
    }
}

// ---------------------------------------------------------------------------
// Kernel 2: C = txt_n @ G^T fused with neg reduction + final loss + cleanup.
// grid = NBLK + NCLEAN blocks, 256 threads.
//   blocks [0, NBLK):      GEMM + neg epilogue; last one computes loss.
//   blocks [NBLK, +NCLEAN): wait for all G reads, then zero G/cnt for replay.
// ---------------------------------------------------------------------------
__global__ void __launch_bounds__(256) gemm_neg_kernel(
    const float* __restrict__ txt,
    float* __restrict__ out)
{
    const int tid = threadIdx.x;

    // ---------------- cleaner blocks ----------------
    if (blockIdx.x >= NBLK) {
        if (tid == 0) {
            // wait until all compute blocks are done reading G / cnt
            while (atomicAdd(&g_tickG, 0u) < (unsigned)NBLK) __nanosleep(128);
        }
        __syncthreads();
        const int cid = blockIdx.x - NBLK;
        const float4 z4 = make_float4(0.f, 0.f, 0.f, 0.f);
        for (int idx = cid * 256 + tid; idx < (NC * D) / 4; idx += NCLEAN * 256)
            reinterpret_cast<float4*>(g_G)[idx] = z4;
        if (cid == 0 && tid < NCP) g_cnt[tid] = 0;
        __threadfence();
        __syncthreads();
        if (tid == 0) {
            unsigned t = atomicAdd(&g_cleandone, 1u);
            if (t == NCLEAN - 1) {           // last cleaner resets tickets
                g_tickG = 0u;
                g_cleandone = 0u;
                __threadfence();
            }
        }
        return;
    }

    // ---------------- compute blocks ----------------
    __shared__ float As[ROWS_B][KT + 1];   // [row][k]
    __shared__ float Bs[KT][NCP + 2];      // [k][class], stride 130
    __shared__ float rs[ROWS_B];           // per-row text scale

    const int lane = tid & 31;
    const int warp = tid >> 5;
    const int row0 = blockIdx.x * ROWS_B;

    if (tid < ROWS_B) rs[tid] = g_rscale[row0 + tid];

    // class counts for this lane's 4 classes (padded -> 0)
    const float n0 = (float)g_cnt[2*lane];
    const float n1 = (float)g_cnt[2*lane + 1];
    const float n2 = (float)g_cnt[2*lane + 64];
    const float n3 = (float)g_cnt[2*lane + 65];

    unsigned long long accp[4][2] = {};

    const int ar  = tid >> 3;            // A row 0..31
    const int ak4 = (tid & 7) * 4;       // A k offset
    const float4 zero4 = make_float4(0.f, 0.f, 0.f, 0.f);

    float4 aReg;
    float4 bReg[4];

    aReg = *reinterpret_cast<const float4*>(&txt[(size_t)(row0 + ar) * D + ak4]);
    #pragma unroll
    for (int e = 0; e < 4; e++) {
        int idx = tid + e * 256;
        int c = idx >> 3, k4 = (idx & 7) * 4;
        bReg[e] = (c < NC)
            ? *reinterpret_cast<const float4*>(&g_G[(size_t)c * D + k4])
            : zero4;
    }
    __syncthreads();   // rs visible

    const float ascale = rs[ar];

    for (int t = 0; t < D / KT; t++) {
        As[ar][ak4 + 0] = aReg.x * ascale;
        As[ar][ak4 + 1] = aReg.y * ascale;
        As[ar][ak4 + 2] = aReg.z * ascale;
        As[ar][ak4 + 3] = aReg.w * ascale;
        #pragma unroll
        for (int e = 0; e < 4; e++) {
            int idx = tid + e * 256;
            int c = idx >> 3, k4 = (idx & 7) * 4;
            Bs[k4 + 0][c] = bReg[e].x;
            Bs[k4 + 1][c] = bReg[e].y;
            Bs[k4 + 2][c] = bReg[e].z;
            Bs[k4 + 3][c] = bReg[e].w;
        }
        __syncthreads();

        if (t < D / KT - 1) {
            int k0 = (t + 1) * KT;
            aReg = *reinterpret_cast<const float4*>(&txt[(size_t)(row0 + ar) * D + k0 + ak4]);
            #pragma unroll
            for (int e = 0; e < 4; e++) {
                int idx = tid + e * 256;
                int c = idx >> 3, k4 = (idx & 7) * 4;
                bReg[e] = (c < NC)
                    ? *reinterpret_cast<const float4*>(&g_G[(size_t)c * D + k0 + k4])
                    : zero4;
            }
        }

        #pragma unroll
        for (int kk = 0; kk < KT; kk++) {
            const unsigned long long b0 =
                *reinterpret_cast<const unsigned long long*>(&Bs[kk][2 * lane]);
            const unsigned long long b1 =
                *reinterpret_cast<const unsigned long long*>(&Bs[kk][2 * lane + 64]);
            #pragma unroll
            for (int ii = 0; ii < 4; ii++) {
                float av = As[warp * 4 + ii][kk];
                unsigned long long ap;
                SPLAT2(ap, av);
                FMA2(accp[ii][0], ap, b0);
                FMA2(accp[ii][1], ap, b1);
            }
        }
        __syncthreads();
    }

    // signal: this block is done reading G / cnt
    if (tid == 0) {
        __threadfence();
        atomicAdd(&g_tickG, 1u);
    }

    // Epilogue: per row i: S = sum_c C[i,c]; neg += sum_c n_c * exp(S - C[i,c])
    double warp_neg = 0.0;
    #pragma unroll
    for (int ii = 0; ii < 4; ii++) {
        float c00, c01, c10, c11;
        asm("mov.b64 {%0, %1}, %2;" : "=f"(c00), "=f"(c01) : "l"(accp[ii][0]));
        asm("mov.b64 {%0, %1}, %2;" : "=f"(c10), "=f"(c11) : "l"(accp[ii][1]));
        float s = c00 + c01 + c10 + c11;
        #pragma unroll
        for (int off = 16; off > 0; off >>= 1)
            s += __shfl_xor_sync(0xffffffffu, s, off);   // S_i allreduce
        float p = n0 * expf(s - c00) + n1 * expf(s - c01)
                + n2 * expf(s - c10) + n3 * expf(s - c11);
        #pragma unroll
        for (int off = 16; off > 0; off >>= 1)
            p += __shfl_xor_sync(0xffffffffu, p, off);
        warp_neg += (double)p;
    }
    __shared__ double bneg[8];
    if (lane == 0) bneg[warp] = warp_neg;
    __syncthreads();

    if (tid == 0) {
        double bsum = 0.0;
        #pragma unroll
        for (int w = 0; w < 8; w++) bsum += bneg[w];
        atomicAdd(&g_neg, bsum);
        __threadfence();
        unsigned t = atomicAdd(&g_fin, 1u);
        if (t == NBLK - 1) {
            // Final: loss = N*log(neg) + sumexp/neg - sumd
            // (exact: sum_i log1p(exp(d_i)/neg) == sumexp/neg to ~1e-10 abs,
            //  since neg >= ~1e5 and exp(d_i) <= e)
            const double neg  = atomicAdd(&g_neg, 0.0);
            const double sd   = atomicAdd(&g_sumd, 0.0);
            const double sexp = atomicAdd(&g_sumexpd, 0.0);
            out[0] = (float)((double)N * log(neg) + sexp / neg - sd);
            // reset scalar accumulators for next replay
            g_neg = 0.0; g_sumd = 0.0; g_sumexpd = 0.0; g_fin = 0u;
            __threadfence();
        }
    }
}

// ---------------------------------------------------------------------------
extern "C" void kernel_launch(void* const* d_in, const int* in_sizes, int n_in,
                              void* d_out, int out_size) {
    const float* img    = (const float*)d_in[0];
    const float* txt    = (const float*)d_in[1];
    const int*   labels = (const int*)d_in[2];
    float* out = (float*)d_out;

    rownorm_kernel<<<N, 128>>>(img, txt, labels);
    gemm_neg_kernel<<<NBLK + NCLEAN, 256>>>(txt, out);
}